// round 8
// baseline (speedup 1.0000x reference)
#include <cuda_runtime.h>
#include <cuda_bf16.h>
#include <cstdint>

#define BB 256
#define NN 200
#define FIN 768
#define HID 32
#define NH 8
#define FCAT 256
#define ALPHA 0.3f
#define BN_EPS 1e-5f
#define ROWS (BB*NN)

__device__ float g_Wc[FIN*FCAT];
__device__ float g_H[ROWS*FCAT];
__device__ float g_s1[ROWS*NH];
__device__ float g_s2[ROWS*NH];
__device__ float g_X[ROWS*FCAT];
__device__ float g_hsent[ROWS*2];
__device__ float g_hpara[ROWS*2];
__device__ float g_hq[ROWS*HID];
__device__ float g_s1s[ROWS], g_s2s[ROWS];
__device__ float g_s1p[ROWS], g_s2p[ROWS];
__device__ float g_s1q[ROWS], g_s2q[ROWS];

__device__ __forceinline__ float wsum32(float v){
    #pragma unroll
    for(int o=16;o;o>>=1) v += __shfl_xor_sync(0xffffffffu,v,o);
    return v;
}
__device__ __forceinline__ float wmax32(float v){
    #pragma unroll
    for(int o=16;o;o>>=1) v = fmaxf(v,__shfl_xor_sync(0xffffffffu,v,o));
    return v;
}
__device__ __forceinline__ float lrelu(float x){ return x>0.f?x:ALPHA*x; }
__device__ __forceinline__ float elu1(float x){ return x>0.f?x:expm1f(x); }
__device__ __forceinline__ void split2(float a,float b,uint32_t&hi,uint32_t&lo){
    __nv_bfloat16 ah=__float2bfloat16_rn(a), bh=__float2bfloat16_rn(b);
    float ar=a-__bfloat162float(ah), br=b-__bfloat162float(bh);
    __nv_bfloat162 H=__halves2bfloat162(ah,bh);
    __nv_bfloat162 L=__floats2bfloat162_rn(ar,br);
    hi=*(uint32_t*)&H; lo=*(uint32_t*)&L;
}

// ---- pack Wcat[k][h*32+j] = Wh[h][k][j] ----
__global__ void pack_wc(const float* __restrict__ Wh){
    int id = blockIdx.x*256 + threadIdx.x;
    int c = id & 255, k = id >> 8;
    g_Wc[id] = Wh[(c>>5)*(FIN*HID) + k*HID + (c&31)];
}

// ---- GEMM: H = feat @ Wc, bf16 hi/lo split (3 MMAs), 128x128 tiles ----
#define MMA_BF16(C,A0,A1,A2,A3,B0,B1) \
  asm volatile("mma.sync.aligned.m16n8k16.row.col.f32.bf16.bf16.f32 " \
    "{%0,%1,%2,%3}, {%4,%5,%6,%7}, {%8,%9}, {%0,%1,%2,%3};" \
    : "+f"(C[0]),"+f"(C[1]),"+f"(C[2]),"+f"(C[3]) \
    : "r"(A0),"r"(A1),"r"(A2),"r"(A3),"r"(B0),"r"(B1))

__global__ __launch_bounds__(256,2) void gemm_bf16x3(const float* __restrict__ A){
    __shared__ uint32_t Ah[128][20], Al[128][20];
    __shared__ uint32_t Bh[16][136], Bl[16][136];
    int tid=threadIdx.x, lane=tid&31, warp=tid>>5;
    int wr=warp&1, wc=warp>>1;
    int m0=blockIdx.x*128, n0=blockIdx.y*128;
    int g=lane>>2, tg=lane&3;
    float c[4][4][4] = {};

    for(int kk=0;kk<FIN;kk+=32){
        #pragma unroll
        for(int r=0;r<4;r++){
            int pos=tid+r*256, row=pos>>3, c4=pos&7;
            float4 v=*(const float4*)(A+(size_t)(m0+row)*FIN+kk+c4*4);
            uint32_t h0,l0,h1,l1;
            split2(v.x,v.y,h0,l0); split2(v.z,v.w,h1,l1);
            *(uint2*)&Ah[row][c4*2]=make_uint2(h0,h1);
            *(uint2*)&Al[row][c4*2]=make_uint2(l0,l1);
        }
        #pragma unroll
        for(int r=0;r<2;r++){
            int pos=tid+r*256, kp=pos>>5, n4=pos&31;
            float4 v0=*(const float4*)(g_Wc+(size_t)(kk+2*kp)*FCAT+n0+n4*4);
            float4 v1=*(const float4*)(g_Wc+(size_t)(kk+2*kp+1)*FCAT+n0+n4*4);
            uint32_t h[4],l[4];
            split2(v0.x,v1.x,h[0],l[0]); split2(v0.y,v1.y,h[1],l[1]);
            split2(v0.z,v1.z,h[2],l[2]); split2(v0.w,v1.w,h[3],l[3]);
            *(uint4*)&Bh[kp][n4*4]=make_uint4(h[0],h[1],h[2],h[3]);
            *(uint4*)&Bl[kp][n4*4]=make_uint4(l[0],l[1],l[2],l[3]);
        }
        __syncthreads();
        #pragma unroll
        for(int s=0;s<2;s++){
            int kp0=s*8;
            uint32_t ah[4][4], al[4][4];
            #pragma unroll
            for(int mf=0;mf<4;mf++){
                int r0=wr*64+mf*16+g;
                ah[mf][0]=Ah[r0][kp0+tg];   ah[mf][1]=Ah[r0+8][kp0+tg];
                ah[mf][2]=Ah[r0][kp0+4+tg]; ah[mf][3]=Ah[r0+8][kp0+4+tg];
                al[mf][0]=Al[r0][kp0+tg];   al[mf][1]=Al[r0+8][kp0+tg];
                al[mf][2]=Al[r0][kp0+4+tg]; al[mf][3]=Al[r0+8][kp0+4+tg];
            }
            #pragma unroll
            for(int nf=0;nf<4;nf++){
                int col=wc*32+nf*8+g;
                uint32_t bh0=Bh[kp0+tg][col], bh1=Bh[kp0+4+tg][col];
                uint32_t bl0=Bl[kp0+tg][col], bl1=Bl[kp0+4+tg][col];
                #pragma unroll
                for(int mf=0;mf<4;mf++){
                    MMA_BF16(c[mf][nf],ah[mf][0],ah[mf][1],ah[mf][2],ah[mf][3],bh0,bh1);
                    MMA_BF16(c[mf][nf],ah[mf][0],ah[mf][1],ah[mf][2],ah[mf][3],bl0,bl1);
                    MMA_BF16(c[mf][nf],al[mf][0],al[mf][1],al[mf][2],al[mf][3],bh0,bh1);
                }
            }
        }
        __syncthreads();
    }
    #pragma unroll
    for(int mf=0;mf<4;mf++){
        int r0=m0+wr*64+mf*16+g;
        #pragma unroll
        for(int nf=0;nf<4;nf++){
            int col=n0+wc*32+nf*8+tg*2;
            *(float2*)(g_H+(size_t)r0*FCAT+col)    =make_float2(c[mf][nf][0],c[mf][nf][1]);
            *(float2*)(g_H+(size_t)(r0+8)*FCAT+col)=make_float2(c[mf][nf][2],c[mf][nf][3]);
        }
    }
}

// ---- per-head scores s1,s2 ----
__global__ __launch_bounds__(256) void head_scores(const float* __restrict__ ah){
    int warp=threadIdx.x>>5, lane=threadIdx.x&31;
    int row=blockIdx.x*8+warp;
    #pragma unroll
    for(int h=0;h<NH;h++){
        float v=g_H[(size_t)row*FCAT+h*32+lane];
        float p1=wsum32(v*ah[h*64+lane]);
        float p2=wsum32(v*ah[h*64+32+lane]);
        if(lane==0){ g_s1[row*NH+h]=p1; g_s2[row*NH+h]=p2; }
    }
}

// ---- fused 8-head softmax attention + ELU + BN ----
#define MI 32
#define TJ 32
struct AttnSmem {
    float4 Hs[TJ][FCAT/4];
    float  wsm[MI*NH][TJ+1];
    float  s2s[NN][NH];
    float  s1s[MI][NH];
    float  msm[MI][NH];
    float  ssum[MI][NH];
    unsigned char adjs[MI][NN];
    int    nval[MI];
};

__global__ __launch_bounds__(256,2) void attn_heads(
        const int* __restrict__ adj,
        const float* __restrict__ bng, const float* __restrict__ bnb,
        const float* __restrict__ bnm, const float* __restrict__ bnv){
    extern __shared__ unsigned char smraw[];
    AttnSmem* sm=(AttnSmem*)smraw;
    int b=blockIdx.y, i0=blockIdx.x*MI, tid=threadIdx.x;

    for(int idx=tid; idx<NN*NH; idx+=256)
        ((float*)sm->s2s)[idx]=g_s2[(size_t)b*NN*NH+idx];
    {
        int i=tid>>3, h=tid&7;
        int ig=min(i0+i,NN-1);
        sm->s1s[i][h]=g_s1[((size_t)b*NN+ig)*NH+h];
    }
    for(int idx=tid; idx<MI*NN; idx+=256){
        int i=idx/NN, j=idx-i*NN;
        int ig=min(i0+i,NN-1);
        sm->adjs[i][j]=(adj[((size_t)b*NN+ig)*NN+j]>0)?1:0;
    }
    __syncthreads();
    {
        int i=tid>>3, h=tid&7;
        float s1v=sm->s1s[i][h];
        float m=-1e30f; int nv=0;
        for(int j=0;j<NN;j++){
            if(sm->adjs[i][j]){ m=fmaxf(m,lrelu(s1v+sm->s2s[j][h])); nv++; }
        }
        sm->msm[i][h]=(nv>0)?m:0.f;
        if(h==0) sm->nval[i]=nv;
    }
    __syncthreads();

    int ti=tid>>6, tf=tid&63, h_f=tf>>3;
    float4 acc[8];
    #pragma unroll
    for(int ii=0;ii<8;ii++) acc[ii]=make_float4(0.f,0.f,0.f,0.f);

    int pi=tid>>3, ph=tid&7;
    float s1v=sm->s1s[pi][ph];
    float mv =sm->msm[pi][ph];
    int   nv =sm->nval[pi];
    bool rowok=(i0+pi)<NN;
    float lsum=0.f;

    for(int jt=0; jt<(NN+TJ-1)/TJ; jt++){
        int j0=jt*TJ;
        __syncthreads();
        #pragma unroll
        for(int r=0;r<8;r++){
            int idx=r*256+tid, j=idx>>6, f4=idx&63;
            int jg=min(j0+j,NN-1);
            sm->Hs[j][f4]=*(const float4*)(g_H+((size_t)b*NN+jg)*FCAT+f4*4);
        }
        #pragma unroll 4
        for(int jj=0;jj<TJ;jj++){
            int jg=j0+jj;
            float w=0.f;
            if(jg<NN && rowok){
                if(sm->adjs[pi][jg]) w=__expf(lrelu(s1v+sm->s2s[jg][ph])-mv);
                else if(nv==0) w=1.f;
            }
            lsum+=w;
            sm->wsm[tid][jj]=w;
        }
        __syncthreads();
        #pragma unroll 4
        for(int jj=0;jj<TJ;jj++){
            float4 hv=sm->Hs[jj][tf];
            #pragma unroll
            for(int ii=0;ii<8;ii++){
                float w=sm->wsm[(ti*8+ii)*NH+h_f][jj];
                acc[ii].x=fmaf(w,hv.x,acc[ii].x);
                acc[ii].y=fmaf(w,hv.y,acc[ii].y);
                acc[ii].z=fmaf(w,hv.z,acc[ii].z);
                acc[ii].w=fmaf(w,hv.w,acc[ii].w);
            }
        }
    }
    sm->ssum[pi][ph]=lsum;
    __syncthreads();
    #pragma unroll
    for(int ii=0;ii<8;ii++){
        int i=ti*8+ii, ig=i0+i;
        if(ig<NN){
            float r=1.f/sm->ssum[i][h_f];
            float inv=bng[ig]*rsqrtf(bnv[ig]+BN_EPS);
            float mean=bnm[ig], beta=bnb[ig];
            float4 o;
            o.x=(elu1(acc[ii].x*r)-mean)*inv+beta;
            o.y=(elu1(acc[ii].y*r)-mean)*inv+beta;
            o.z=(elu1(acc[ii].z*r)-mean)*inv+beta;
            o.w=(elu1(acc[ii].w*r)-mean)*inv+beta;
            *(float4*)(g_X+((size_t)b*NN+ig)*FCAT+tf*4)=o;
        }
    }
}

// ---- stage-2 projections + scores ----
__global__ __launch_bounds__(256) void stage2_proj(
        const float* __restrict__ Wsent, const float* __restrict__ asent,
        const float* __restrict__ Wpara, const float* __restrict__ apara,
        const float* __restrict__ Wqt,   const float* __restrict__ aqt){
    __shared__ float Wq_s[FCAT*HID];
    __shared__ float Ws_s[FCAT*2], Wp_s[FCAT*2];
    __shared__ float as_s[4], ap_s[4], aq_s[64];
    int tid=threadIdx.x;
    for(int idx=tid; idx<FCAT*HID; idx+=256) Wq_s[idx]=Wqt[idx];
    for(int idx=tid; idx<FCAT*2;   idx+=256){ Ws_s[idx]=Wsent[idx]; Wp_s[idx]=Wpara[idx]; }
    if(tid<4){ as_s[tid]=asent[tid]; ap_s[tid]=apara[tid]; }
    if(tid<64) aq_s[tid]=aqt[tid];
    __syncthreads();

    int warp=tid>>5, lane=tid&31;
    int row=blockIdx.x*8+warp;
    float x[8];
    #pragma unroll
    for(int q=0;q<8;q++) x[q]=g_X[(size_t)row*FCAT+q*32+lane];

    float hs0=0,hs1=0,hp0=0,hp1=0;
    #pragma unroll
    for(int q=0;q<8;q++){
        int k=q*32+lane;
        hs0=fmaf(x[q],Ws_s[k*2+0],hs0); hs1=fmaf(x[q],Ws_s[k*2+1],hs1);
        hp0=fmaf(x[q],Wp_s[k*2+0],hp0); hp1=fmaf(x[q],Wp_s[k*2+1],hp1);
    }
    hs0=wsum32(hs0); hs1=wsum32(hs1); hp0=wsum32(hp0); hp1=wsum32(hp1);
    if(lane==0){
        g_hsent[row*2]=hs0; g_hsent[row*2+1]=hs1;
        g_hpara[row*2]=hp0; g_hpara[row*2+1]=hp1;
        g_s1s[row]=hs0*as_s[0]+hs1*as_s[1];
        g_s2s[row]=hs0*as_s[2]+hs1*as_s[3];
        g_s1p[row]=hp0*ap_s[0]+hp1*ap_s[1];
        g_s2p[row]=hp0*ap_s[2]+hp1*ap_s[3];
    }
    float hq=0.f;
    #pragma unroll
    for(int q=0;q<8;q++)
        #pragma unroll
        for(int l=0;l<32;l++){
            float xv=__shfl_sync(0xffffffffu,x[q],l);
            hq=fmaf(xv,Wq_s[(q*32+l)*HID+lane],hq);
        }
    g_hq[(size_t)row*HID+lane]=hq;
    float p1=wsum32(hq*aq_s[lane]);
    float p2=wsum32(hq*aq_s[32+lane]);
    if(lane==0){ g_s1q[row]=p1; g_s2q[row]=p2; }
}

// ---- sent & para attention + activations ----
__global__ __launch_bounds__(256) void stage2_attn(const int* __restrict__ adj,
                                                   float* __restrict__ out){
    int warp=threadIdx.x>>5, lane=threadIdx.x&31;
    int row=blockIdx.x*8+warp;
    int b=row/NN, i=row-b*NN;
    const int* arow=adj+((size_t)b*NN+i)*NN;
    float s1se=g_s1s[row], s1pa=g_s1p[row];

    float ms=-1e30f, mp=-1e30f; int nv=0;
    #pragma unroll
    for(int t=0;t<7;t++){
        int j=lane+t*32;
        if(j<NN && arow[j]>0){
            nv++;
            ms=fmaxf(ms,lrelu(s1se+g_s2s[b*NN+j]));
            mp=fmaxf(mp,lrelu(s1pa+g_s2p[b*NN+j]));
        }
    }
    ms=wmax32(ms); mp=wmax32(mp);
    nv=__reduce_add_sync(0xffffffffu,nv);

    float a0=0,a1=0,as=0,p0=0,p1=0,ps=0;
    #pragma unroll
    for(int t=0;t<7;t++){
        int j=lane+t*32;
        if(j<NN){
            bool msk=arow[j]>0;
            float ws=msk?__expf(lrelu(s1se+g_s2s[b*NN+j])-ms):(nv==0?1.f:0.f);
            float wp=msk?__expf(lrelu(s1pa+g_s2p[b*NN+j])-mp):(nv==0?1.f:0.f);
            const float* hs=g_hsent+(size_t)(b*NN+j)*2;
            const float* hp=g_hpara+(size_t)(b*NN+j)*2;
            a0=fmaf(ws,hs[0],a0); a1=fmaf(ws,hs[1],a1); as+=ws;
            p0=fmaf(wp,hp[0],p0); p1=fmaf(wp,hp[1],p1); ps+=wp;
        }
    }
    a0=wsum32(a0); a1=wsum32(a1); as=wsum32(as);
    p0=wsum32(p0); p1=wsum32(p1); ps=wsum32(ps);
    if(lane==0){
        out[row*2+0]=1.f/(1.f+__expf(-a0/as));
        out[row*2+1]=1.f/(1.f+__expf(-a1/as));
        out[ROWS*2+row*2+0]=elu1(p0/ps);
        out[ROWS*2+row*2+1]=elu1(p1/ps);
    }
}

// ---- qtype head (row 0 only) ----
__global__ __launch_bounds__(256) void stage2_qt(const int* __restrict__ adj,
                                                 const float* __restrict__ W2,
                                                 float* __restrict__ out){
    __shared__ float W2s[64];
    int warp=threadIdx.x>>5, lane=threadIdx.x&31;
    if(threadIdx.x<64) W2s[threadIdx.x]=W2[threadIdx.x];
    __syncthreads();
    int b=blockIdx.x*8+warp;
    const int* arow=adj+(size_t)b*NN*NN;
    int row0=b*NN;
    float s1=g_s1q[row0];

    float m=-1e30f; int nv=0;
    #pragma unroll
    for(int t=0;t<7;t++){
        int j=lane+t*32;
        if(j<NN && arow[j]>0){ nv++; m=fmaxf(m,lrelu(s1+g_s2q[row0+j])); }
    }
    m=wmax32(m);
    nv=__reduce_add_sync(0xffffffffu,nv);

    float acc=0.f, ws=0.f;
    for(int j=0;j<NN;j++){
        float w;
        if(arow[j]>0) w=__expf(lrelu(s1+g_s2q[row0+j])-m);
        else w=(nv==0)?1.f:0.f;
        acc=fmaf(w,g_hq[(size_t)(row0+j)*HID+lane],acc);
        ws+=w;
    }
    float h=acc/ws;
    float l0=wsum32(h*W2s[lane*2+0]);
    float l1=wsum32(h*W2s[lane*2+1]);
    if(lane==0){
        out[ROWS*4+b*2+0]=elu1(l0);
        out[ROWS*4+b*2+1]=elu1(l1);
    }
}

extern "C" void kernel_launch(void* const* d_in, const int* in_sizes, int n_in,
                              void* d_out, int out_size){
    const float* feat =(const float*)d_in[0];
    const int*   adj  =(const int*)  d_in[1];
    const float* Wh   =(const float*)d_in[2];
    const float* ah   =(const float*)d_in[3];
    const float* Wsent=(const float*)d_in[4];
    const float* asent=(const float*)d_in[5];
    const float* Wpara=(const float*)d_in[6];
    const float* apara=(const float*)d_in[7];
    const float* Wqt  =(const float*)d_in[8];
    const float* aqt  =(const float*)d_in[9];
    const float* W2   =(const float*)d_in[10];
    const float* bng  =(const float*)d_in[11];
    const float* bnb  =(const float*)d_in[12];
    const float* bnm  =(const float*)d_in[13];
    const float* bnv  =(const float*)d_in[14];
    float* out=(float*)d_out;

    pack_wc<<<FIN*FCAT/256,256>>>(Wh);
    gemm_bf16x3<<<dim3(ROWS/128,FCAT/128),256>>>(feat);
    head_scores<<<ROWS/8,256>>>(ah);
    cudaFuncSetAttribute(attn_heads, cudaFuncAttributeMaxDynamicSharedMemorySize,
                         (int)sizeof(AttnSmem));
    attn_heads<<<dim3((NN+MI-1)/MI,BB),256,sizeof(AttnSmem)>>>(adj,bng,bnb,bnm,bnv);
    stage2_proj<<<ROWS/8,256>>>(Wsent,asent,Wpara,apara,Wqt,aqt);
    stage2_attn<<<ROWS/8,256>>>(adj,out);
    stage2_qt<<<BB/8,256>>>(adj,W2,out);
}